// round 7
// baseline (speedup 1.0000x reference)
#include <cuda_runtime.h>
#include <cstdint>

// ============================================================================
// Monte-Carlo E[softmax(mean + eps)], JAX threefry-partitionable bit-exact RNG.
// R7: rotate-via-IMAD.WIDE done FOR REAL — rotation multipliers (1<<r) passed
// as OPAQUE runtime params (uint4), so ptxas cannot strength-reduce them back
// to SHF. 12 of 20 rounds (rot 13,15,26,6) use mul.wide.u32 + single fused
// LOP3 merge; 8 rounds (17,29,16,24) stay SHF. alu/eval ~46 -> ~34 ops.
// ============================================================================

#define NROWS 16384
#define NCOLS 512
#define WARPS_PER_BLOCK 8
#define NTHREADS (WARPS_PER_BLOCK * 32)
#define KPL 16
#define MAX_SAMPLES 512

// a + b on the integer-MAD pipe: a*one + b, `one` opaque to ptxas.
__device__ __forceinline__ uint32_t madd(uint32_t a, uint32_t b, uint32_t one) {
    uint32_t t;
    asm("mad.lo.u32 %0, %1, %2, %3;" : "=r"(t) : "r"(a), "r"(one), "r"(b));
    return t;
}

// rotl via SHF (alu) then fused xor (alu LOP3): 2 alu ops.
__device__ __forceinline__ uint32_t rots(uint32_t x1, int r, uint32_t x0) {
    return __funnelshift_l(x1, x1, r) ^ x0;
}
// rotl via mul.wide.u32 with OPAQUE multiplier m = 1<<r (IMAD.WIDE, imad pipe),
// merge (lo|hi)^x0 is ONE LOP3 (alu): 1 imad + 1 alu.
__device__ __forceinline__ uint32_t rotw(uint32_t x1, uint32_t m, uint32_t x0) {
    unsigned long long w;
    asm("mul.wide.u32 %0, %1, %2;" : "=l"(w) : "r"(x1), "r"(m));
    return (((uint32_t)w) | ((uint32_t)(w >> 32))) ^ x0;
}

// Compile-time threefry for per-sample subkeys (amortized, per block).
__device__ __forceinline__ void tf_round_c(uint32_t& x0, uint32_t& x1, int r) {
    x0 += x1;
    x1 = __funnelshift_l(x1, x1, r);
    x1 ^= x0;
}
__device__ __forceinline__ uint2 threefry2x32_c(uint32_t k0, uint32_t k1,
                                                uint32_t c0, uint32_t c1) {
    uint32_t k2 = k0 ^ k1 ^ 0x1BD11BDAu;
    uint32_t x0 = c0 + k0;
    uint32_t x1 = c1 + k1;
    tf_round_c(x0,x1,13); tf_round_c(x0,x1,15); tf_round_c(x0,x1,26); tf_round_c(x0,x1,6);
    x0 += k1; x1 += k2 + 1u;
    tf_round_c(x0,x1,17); tf_round_c(x0,x1,29); tf_round_c(x0,x1,16); tf_round_c(x0,x1,24);
    x0 += k2; x1 += k0 + 2u;
    tf_round_c(x0,x1,13); tf_round_c(x0,x1,15); tf_round_c(x0,x1,26); tf_round_c(x0,x1,6);
    x0 += k0; x1 += k1 + 3u;
    tf_round_c(x0,x1,17); tf_round_c(x0,x1,29); tf_round_c(x0,x1,16); tf_round_c(x0,x1,24);
    x0 += k1; x1 += k2 + 4u;
    tf_round_c(x0,x1,13); tf_round_c(x0,x1,15); tf_round_c(x0,x1,26); tf_round_c(x0,x1,6);
    x0 += k2; x1 += k0 + 5u;
    return make_uint2(x0, x1);
}

// Hot fold, counter (0, c1), x1 passed pre-added (c1 + k1). Returns x0^x1.
// A-groups (13,15,26,6) -> rotw (opaque multipliers rm.x/y/z/w);
// B-groups (17,29,16,24) -> rots. x0-injections fused into IADD3.
__device__ __forceinline__ uint32_t tf_fold(
    uint32_t k0, uint32_t k1, uint32_t k2,
    uint32_t i1, uint32_t i2, uint32_t i3, uint32_t i4, uint32_t i5,
    uint32_t x1, uint32_t one, uint4 rm)
{
    uint32_t x0;
    // G1 (wide): rot 13,15,26,6
    x0 = madd(x1, k0, one);          x1 = rotw(x1, rm.x, x0);
    x0 = madd(x1, x0, one);          x1 = rotw(x1, rm.y, x0);
    x0 = madd(x1, x0, one);          x1 = rotw(x1, rm.z, x0);
    x0 = madd(x1, x0, one);          x1 = rotw(x1, rm.w, x0);
    // inject (k1, i1); x0-inject fused into IADD3 with round add
    x1 = madd(i1, x1, one);
    x0 = x0 + k1 + x1;               x1 = rots(x1, 17, x0);
    x0 = madd(x1, x0, one);          x1 = rots(x1, 29, x0);
    x0 = madd(x1, x0, one);          x1 = rots(x1, 16, x0);
    x0 = madd(x1, x0, one);          x1 = rots(x1, 24, x0);
    // inject (k2, i2)
    x1 = madd(i2, x1, one);
    x0 = x0 + k2 + x1;               x1 = rotw(x1, rm.x, x0);
    x0 = madd(x1, x0, one);          x1 = rotw(x1, rm.y, x0);
    x0 = madd(x1, x0, one);          x1 = rotw(x1, rm.z, x0);
    x0 = madd(x1, x0, one);          x1 = rotw(x1, rm.w, x0);
    // inject (k0, i3)
    x1 = madd(i3, x1, one);
    x0 = x0 + k0 + x1;               x1 = rots(x1, 17, x0);
    x0 = madd(x1, x0, one);          x1 = rots(x1, 29, x0);
    x0 = madd(x1, x0, one);          x1 = rots(x1, 16, x0);
    x0 = madd(x1, x0, one);          x1 = rots(x1, 24, x0);
    // inject (k1, i4)
    x1 = madd(i4, x1, one);
    x0 = x0 + k1 + x1;               x1 = rotw(x1, rm.x, x0);
    x0 = madd(x1, x0, one);          x1 = rotw(x1, rm.y, x0);
    x0 = madd(x1, x0, one);          x1 = rotw(x1, rm.z, x0);
    x0 = madd(x1, x0, one);          x1 = rotw(x1, rm.w, x0);
    // final inject (k2, i5) + output xor
    return madd(k2, x0, one) ^ madd(i5, x1, one);
}

// One element eval: threefry bits -> uniform -> erfinv -> exp2 value.
__device__ __forceinline__ float eval_one(
    uint32_t k0, uint32_t k1, uint32_t k2,
    uint32_t i1, uint32_t i2, uint32_t i3, uint32_t i4, uint32_t i5,
    uint32_t x1init, uint32_t one, uint4 rm, float m2v, float s3v)
{
    const float LO = __int_as_float(0xBF7FFFFF);  // nextafter(-1, 0)
    uint32_t bits = tf_fold(k0, k1, k2, i1, i2, i3, i4, i5, x1init, one, rm);
    // m = bits >> 9; exact I2F; single-rounded u (bit-identical to XLA path).
    float mf = (float)(bits >> 9);
    float u = fmaf(mf, 0x1p-22f, LO);
    // XLA ErfInv (Giles), 7-term main branch (validated R5); rare tail.
    float t = fmaf(-u, u, 1.0f);
    float lg;
    asm("lg2.approx.f32 %0, %1;" : "=f"(lg) : "f"(t));
    float ww = fmaf(lg, -0.6931471805599453f, -2.5f);  // w - 2.5
    float p = -3.5233877e-06f;
    p = fmaf(p, ww, -4.39150654e-06f);
    p = fmaf(p, ww, 0.00021858087f);
    p = fmaf(p, ww, -0.00125372503f);
    p = fmaf(p, ww, -0.00417768164f);
    p = fmaf(p, ww, 0.246640727f);
    p = fmaf(p, ww, 1.50140941f);
    if (__builtin_expect(!!(lg <= -7.2134752044448170f), 0)) {  // w >= 5
        float w = lg * -0.6931471805599453f;
        float sw;
        asm("sqrt.approx.f32 %0, %1;" : "=f"(sw) : "f"(w));
        float v = sw - 3.0f;
        p = -0.000200214257f;
        p = fmaf(p, v, 0.000100950558f);
        p = fmaf(p, v, 0.00134934322f);
        p = fmaf(p, v, -0.00367342844f);
        p = fmaf(p, v, 0.00573950773f);
        p = fmaf(p, v, -0.0076224613f);
        p = fmaf(p, v, 0.00943887047f);
        p = fmaf(p, v, 1.00167406f);
        p = fmaf(p, v, 2.83297682f);
    }
    float g = p * u;                 // erfinv(u)
    float tt = fmaf(g, s3v, m2v);    // (mean + eps) * log2(e)
    float ev;
    asm("ex2.approx.f32 %0, %1;" : "=f"(ev) : "f"(tt));
    return ev;
}

__global__ void __launch_bounds__(NTHREADS, 4)
mc_softmax_kernel(const float* __restrict__ mean,
                  const float* __restrict__ var,
                  const int* __restrict__ d_ns,
                  float* __restrict__ out,
                  uint32_t one, uint4 rm) {
    // (m2_{2j}, m2_{2j+1}, s3_{2j}, s3_{2j+1}) per thread -> one LDS.128/pair.
    __shared__ float4 ms4[(KPL / 2) * NTHREADS];  // 32 KB
    __shared__ uint2 skeys[MAX_SAMPLES];          //  4 KB

    int ns = d_ns ? *d_ns : 400;
    if (ns > MAX_SAMPLES) ns = MAX_SAMPLES;

    int tid = threadIdx.x;
    for (int s = tid; s < ns; s += NTHREADS)
        skeys[s] = threefry2x32_c(0u, 42u, 0u, (uint32_t)s);

    int warp = tid >> 5;
    int lane = tid & 31;
    int row = blockIdx.x * WARPS_PER_BLOCK + warp;
    int base = row * NCOLS + lane;

    const float LOG2E = 1.4426950408889634f;
    const float S2LOG2E = 1.41421356237309504880f * 1.4426950408889634f;

    float acc[KPL];
#pragma unroll
    for (int j = 0; j < KPL / 2; j++) {
        int ia = base + 32 * (2 * j);
        int ib = base + 32 * (2 * j + 1);
        float4 v;
        v.x = mean[ia] * LOG2E;
        v.y = mean[ib] * LOG2E;
        v.z = sqrtf(var[ia]) * S2LOG2E;
        v.w = sqrtf(var[ib]) * S2LOG2E;
        ms4[j * NTHREADS + tid] = v;
        acc[2 * j] = 0.0f;
        acc[2 * j + 1] = 0.0f;
    }
    __syncthreads();

    for (int s = 0; s < ns; s++) {
        uint2 key = skeys[s];
        uint32_t k0 = key.x, k1 = key.y;
        uint32_t k2 = k0 ^ k1 ^ 0x1BD11BDAu;
        uint32_t i1 = k2 + 1u, i2 = k0 + 2u, i3 = k1 + 3u,
                 i4 = k2 + 4u, i5 = k0 + 5u;
        uint32_t cb = (uint32_t)base + k1;  // x1_init = counter + k1

        float e[KPL];
        float part = 0.0f;
#pragma unroll
        for (int j = 0; j < KPL / 2; j++) {
            float4 msk = ms4[j * NTHREADS + tid];
            float ea = eval_one(k0, k1, k2, i1, i2, i3, i4, i5,
                                cb + 32u * (uint32_t)(2 * j), one, rm,
                                msk.x, msk.z);
            float eb = eval_one(k0, k1, k2, i1, i2, i3, i4, i5,
                                cb + 32u * (uint32_t)(2 * j + 1), one, rm,
                                msk.y, msk.w);
            e[2 * j] = ea;
            e[2 * j + 1] = eb;
            part += ea;
            part += eb;
        }
#pragma unroll
        for (int o = 16; o > 0; o >>= 1)
            part += __shfl_xor_sync(0xffffffffu, part, o);
        float rinv;
        asm("rcp.approx.f32 %0, %1;" : "=f"(rinv) : "f"(part));
#pragma unroll
        for (int k = 0; k < KPL; k++)
            acc[k] = fmaf(e[k], rinv, acc[k]);
    }

    float inv = 1.0f / (float)ns;
#pragma unroll
    for (int k = 0; k < KPL; k++)
        out[base + 32 * k] = acc[k] * inv;
}

extern "C" void kernel_launch(void* const* d_in, const int* in_sizes, int n_in,
                              void* d_out, int out_size) {
    const float* mean = (const float*)d_in[0];
    const float* var = (const float*)d_in[1];
    const int* ns = (n_in >= 3) ? (const int*)d_in[2] : nullptr;
    float* out = (float*)d_out;

    // Opaque rotation multipliers 1<<{13,15,26,6} — runtime values so ptxas
    // cannot strength-reduce mul.wide back to SHF.
    uint4 rm = make_uint4(1u << 13, 1u << 15, 1u << 26, 1u << 6);

    dim3 grid(NROWS / WARPS_PER_BLOCK);
    dim3 block(NTHREADS);
    mc_softmax_kernel<<<grid, block>>>(mean, var, ns, out, 1u, rm);
}

// round 8
// speedup vs baseline: 1.0717x; 1.0717x over previous
#include <cuda_runtime.h>
#include <cstdint>

// ============================================================================
// Monte-Carlo E[softmax(mean + eps)], JAX threefry-partitionable bit-exact RNG.
// R8 (base = R6 threefry, best mix): occupancy/latency fix —
//   each row split across 2 warps (KPL=8), halving e[]/acc[] register load;
//   cross-warp row sum via double-buffered shared slot + 1 syncthreads/sample;
//   __launch_bounds__(256,5) -> 51-reg cap -> 5 CTAs/SM (occ ~60%).
// ============================================================================

#define NROWS 16384
#define NCOLS 512
#define NTHREADS 256
#define WARPS 8              // per block
#define ROWS_PER_BLOCK 4     // 2 warps per row
#define KPL 8                // elements per lane (256 cols per warp)
#define MAX_SAMPLES 512

// a + b on the integer-MAD pipe: a*one + b, `one` opaque to ptxas.
__device__ __forceinline__ uint32_t madd(uint32_t a, uint32_t b, uint32_t one) {
    uint32_t t;
    asm("mad.lo.u32 %0, %1, %2, %3;" : "=r"(t) : "r"(a), "r"(one), "r"(b));
    return t;
}

// rotl via SHF (alu) + fused xor (alu LOP3).
__device__ __forceinline__ uint32_t rots(uint32_t x1, int r, uint32_t x0) {
    return __funnelshift_l(x1, x1, r) ^ x0;
}

// Compile-time threefry for per-sample subkeys (amortized, per block).
__device__ __forceinline__ void tf_round_c(uint32_t& x0, uint32_t& x1, int r) {
    x0 += x1;
    x1 = __funnelshift_l(x1, x1, r);
    x1 ^= x0;
}
__device__ __forceinline__ uint2 threefry2x32_c(uint32_t k0, uint32_t k1,
                                                uint32_t c0, uint32_t c1) {
    uint32_t k2 = k0 ^ k1 ^ 0x1BD11BDAu;
    uint32_t x0 = c0 + k0;
    uint32_t x1 = c1 + k1;
    tf_round_c(x0,x1,13); tf_round_c(x0,x1,15); tf_round_c(x0,x1,26); tf_round_c(x0,x1,6);
    x0 += k1; x1 += k2 + 1u;
    tf_round_c(x0,x1,17); tf_round_c(x0,x1,29); tf_round_c(x0,x1,16); tf_round_c(x0,x1,24);
    x0 += k2; x1 += k0 + 2u;
    tf_round_c(x0,x1,13); tf_round_c(x0,x1,15); tf_round_c(x0,x1,26); tf_round_c(x0,x1,6);
    x0 += k0; x1 += k1 + 3u;
    tf_round_c(x0,x1,17); tf_round_c(x0,x1,29); tf_round_c(x0,x1,16); tf_round_c(x0,x1,24);
    x0 += k1; x1 += k2 + 4u;
    tf_round_c(x0,x1,13); tf_round_c(x0,x1,15); tf_round_c(x0,x1,26); tf_round_c(x0,x1,6);
    x0 += k2; x1 += k0 + 5u;
    return make_uint2(x0, x1);
}

// Hot fold (R6): counter (0, c1), x1 passed pre-added (c1 + k1). Returns x0^x1.
// SHF rotates; x0-key-injections fused into 3-input IADD3; round adds on IMAD.
__device__ __forceinline__ uint32_t tf_fold(
    uint32_t k0, uint32_t k1, uint32_t k2,
    uint32_t i1, uint32_t i2, uint32_t i3, uint32_t i4, uint32_t i5,
    uint32_t x1, uint32_t one)
{
    uint32_t x0;
    x0 = madd(x1, k0, one);          x1 = rots(x1, 13, x0);
    x0 = madd(x1, x0, one);          x1 = rots(x1, 15, x0);
    x0 = madd(x1, x0, one);          x1 = rots(x1, 26, x0);
    x0 = madd(x1, x0, one);          x1 = rots(x1,  6, x0);
    x1 = madd(i1, x1, one);
    x0 = x0 + k1 + x1;               x1 = rots(x1, 17, x0);
    x0 = madd(x1, x0, one);          x1 = rots(x1, 29, x0);
    x0 = madd(x1, x0, one);          x1 = rots(x1, 16, x0);
    x0 = madd(x1, x0, one);          x1 = rots(x1, 24, x0);
    x1 = madd(i2, x1, one);
    x0 = x0 + k2 + x1;               x1 = rots(x1, 13, x0);
    x0 = madd(x1, x0, one);          x1 = rots(x1, 15, x0);
    x0 = madd(x1, x0, one);          x1 = rots(x1, 26, x0);
    x0 = madd(x1, x0, one);          x1 = rots(x1,  6, x0);
    x1 = madd(i3, x1, one);
    x0 = x0 + k0 + x1;               x1 = rots(x1, 17, x0);
    x0 = madd(x1, x0, one);          x1 = rots(x1, 29, x0);
    x0 = madd(x1, x0, one);          x1 = rots(x1, 16, x0);
    x0 = madd(x1, x0, one);          x1 = rots(x1, 24, x0);
    x1 = madd(i4, x1, one);
    x0 = x0 + k1 + x1;               x1 = rots(x1, 13, x0);
    x0 = madd(x1, x0, one);          x1 = rots(x1, 15, x0);
    x0 = madd(x1, x0, one);          x1 = rots(x1, 26, x0);
    x0 = madd(x1, x0, one);          x1 = rots(x1,  6, x0);
    return (x0 + k2) ^ madd(i5, x1, one);
}

// One element eval: threefry bits -> uniform -> erfinv -> exp2 value.
__device__ __forceinline__ float eval_one(
    uint32_t k0, uint32_t k1, uint32_t k2,
    uint32_t i1, uint32_t i2, uint32_t i3, uint32_t i4, uint32_t i5,
    uint32_t x1init, uint32_t one, float m2v, float s3v)
{
    const float LO = __int_as_float(0xBF7FFFFF);  // nextafter(-1, 0)
    uint32_t bits = tf_fold(k0, k1, k2, i1, i2, i3, i4, i5, x1init, one);
    float mf = (float)__umulhi(bits, 0x00800000u);  // bits >> 9, imad pipe
    float u = fmaf(mf, 0x1p-22f, LO);
    // XLA ErfInv (Giles), 7-term main branch (validated); rare tail.
    float t = fmaf(-u, u, 1.0f);
    float lg;
    asm("lg2.approx.f32 %0, %1;" : "=f"(lg) : "f"(t));
    float ww = fmaf(lg, -0.6931471805599453f, -2.5f);  // w - 2.5
    float p = -3.5233877e-06f;
    p = fmaf(p, ww, -4.39150654e-06f);
    p = fmaf(p, ww, 0.00021858087f);
    p = fmaf(p, ww, -0.00125372503f);
    p = fmaf(p, ww, -0.00417768164f);
    p = fmaf(p, ww, 0.246640727f);
    p = fmaf(p, ww, 1.50140941f);
    if (__builtin_expect(!!(lg <= -7.2134752044448170f), 0)) {  // w >= 5
        float w = lg * -0.6931471805599453f;
        float sw;
        asm("sqrt.approx.f32 %0, %1;" : "=f"(sw) : "f"(w));
        float v = sw - 3.0f;
        p = -0.000200214257f;
        p = fmaf(p, v, 0.000100950558f);
        p = fmaf(p, v, 0.00134934322f);
        p = fmaf(p, v, -0.00367342844f);
        p = fmaf(p, v, 0.00573950773f);
        p = fmaf(p, v, -0.0076224613f);
        p = fmaf(p, v, 0.00943887047f);
        p = fmaf(p, v, 1.00167406f);
        p = fmaf(p, v, 2.83297682f);
    }
    float g = p * u;                 // erfinv(u)
    float tt = fmaf(g, s3v, m2v);    // (mean + eps) * log2(e)
    float ev;
    asm("ex2.approx.f32 %0, %1;" : "=f"(ev) : "f"(tt));
    return ev;
}

__global__ void __launch_bounds__(NTHREADS, 5)
mc_softmax_kernel(const float* __restrict__ mean,
                  const float* __restrict__ var,
                  const int* __restrict__ d_ns,
                  float* __restrict__ out,
                  uint32_t one) {
    // (m2_a, m2_b, s3_a, s3_b) per thread per pair -> LDS.128.
    __shared__ float4 ms4[(KPL / 2) * NTHREADS];  // 16 KB
    __shared__ uint2 skeys[MAX_SAMPLES];          //  4 KB
    __shared__ float spart[2][WARPS];             // double-buffered partials

    int ns = d_ns ? *d_ns : 400;
    if (ns > MAX_SAMPLES) ns = MAX_SAMPLES;

    int tid = threadIdx.x;
    for (int s = tid; s < ns; s += NTHREADS)
        skeys[s] = threefry2x32_c(0u, 42u, 0u, (uint32_t)s);

    int warp = tid >> 5;
    int lane = tid & 31;
    int rowInBlk = warp >> 1;       // 2 warps per row
    int half = warp & 1;            // which 256-col half
    int row = blockIdx.x * ROWS_PER_BLOCK + rowInBlk;
    int base = row * NCOLS + half * (NCOLS / 2) + lane;

    const float LOG2E = 1.4426950408889634f;
    const float S2LOG2E = 1.41421356237309504880f * 1.4426950408889634f;

    float acc[KPL];
#pragma unroll
    for (int j = 0; j < KPL / 2; j++) {
        int ia = base + 32 * (2 * j);
        int ib = base + 32 * (2 * j + 1);
        float4 v;
        v.x = mean[ia] * LOG2E;
        v.y = mean[ib] * LOG2E;
        v.z = sqrtf(var[ia]) * S2LOG2E;
        v.w = sqrtf(var[ib]) * S2LOG2E;
        ms4[j * NTHREADS + tid] = v;
        acc[2 * j] = 0.0f;
        acc[2 * j + 1] = 0.0f;
    }
    __syncthreads();

    for (int s = 0; s < ns; s++) {
        uint2 key = skeys[s];
        uint32_t k0 = key.x, k1 = key.y;
        uint32_t k2 = k0 ^ k1 ^ 0x1BD11BDAu;
        uint32_t i1 = k2 + 1u, i2 = k0 + 2u, i3 = k1 + 3u,
                 i4 = k2 + 4u, i5 = k0 + 5u;
        uint32_t cb = (uint32_t)base + k1;  // x1_init = counter + k1

        float e[KPL];
        float part = 0.0f;
#pragma unroll
        for (int j = 0; j < KPL / 2; j++) {
            float4 msk = ms4[j * NTHREADS + tid];
            float ea = eval_one(k0, k1, k2, i1, i2, i3, i4, i5,
                                cb + 32u * (uint32_t)(2 * j), one, msk.x, msk.z);
            float eb = eval_one(k0, k1, k2, i1, i2, i3, i4, i5,
                                cb + 32u * (uint32_t)(2 * j + 1), one, msk.y, msk.w);
            e[2 * j] = ea;
            e[2 * j + 1] = eb;
            part += ea;
            part += eb;
        }
        // intra-warp allreduce (half-row sum in every lane)
#pragma unroll
        for (int o = 16; o > 0; o >>= 1)
            part += __shfl_xor_sync(0xffffffffu, part, o);
        // cross-warp pair sum: double-buffered slot, ONE sync per sample.
        int buf = s & 1;
        if (lane == 0) spart[buf][warp] = part;
        __syncthreads();
        float total = part + spart[buf][warp ^ 1];
        float rinv;
        asm("rcp.approx.f32 %0, %1;" : "=f"(rinv) : "f"(total));
#pragma unroll
        for (int k = 0; k < KPL; k++)
            acc[k] = fmaf(e[k], rinv, acc[k]);
    }

    float inv = 1.0f / (float)ns;
#pragma unroll
    for (int k = 0; k < KPL; k++)
        out[base + 32 * k] = acc[k] * inv;
}

extern "C" void kernel_launch(void* const* d_in, const int* in_sizes, int n_in,
                              void* d_out, int out_size) {
    const float* mean = (const float*)d_in[0];
    const float* var = (const float*)d_in[1];
    const int* ns = (n_in >= 3) ? (const int*)d_in[2] : nullptr;
    float* out = (float*)d_out;

    dim3 grid(NROWS / ROWS_PER_BLOCK);
    dim3 block(NTHREADS);
    mc_softmax_kernel<<<grid, block>>>(mean, var, ns, out, 1u);
}